// round 3
// baseline (speedup 1.0000x reference)
#include <cuda_runtime.h>
#include <cuda_bf16.h>
#include <math.h>

#define MAXN 10000
#define MAXE 640000
#define FDIM 128

// ---------------- device scratch (no allocation allowed) ----------------
__device__ __align__(16) float g_deg[MAXN];
__device__ __align__(16) float g_dinv[MAXN];
__device__ __align__(16) int   g_cnt[MAXN];
__device__ __align__(16) int   g_off[MAXN + 1];
__device__ __align__(16) int   g_cursor[MAXN];
__device__ __align__(16) int   g_csr_src[MAXE];
__device__ __align__(16) float g_csr_norm[MAXE];
__device__ __align__(16) float g_Y[MAXN * FDIM];
__device__ __align__(16) float g_Wall[256 * 512];   // [k][g*128+j]
__device__ __align__(16) float g_ball[512];
__device__ __align__(16) float g_pre[MAXN * 512];

__device__ __forceinline__ int clampi(int v, int n) {
    return v < 0 ? 0 : (v >= n ? n - 1 : v);
}

// ---------------- graph norm / CSR build ----------------
__global__ void k_init(int N) {
    int n = blockIdx.x * blockDim.x + threadIdx.x;
    if (n < N) { g_deg[n] = 1.0f; g_cnt[n] = 0; }   // self-loop weight 1
}

__global__ void k_edge_deg(const int* __restrict__ ei,
                           const float* __restrict__ w, int E, int N) {
    int e = blockIdx.x * blockDim.x + threadIdx.x;
    if (e >= E) return;
    int d = clampi(ei[E + e], N);
    atomicAdd(&g_deg[d], w[e]);
    atomicAdd(&g_cnt[d], 1);
}

__global__ void k_dinv(int N) {
    int n = blockIdx.x * blockDim.x + threadIdx.x;
    if (n >= N) return;
    float dg = g_deg[n];
    g_dinv[n] = dg > 0.f ? rsqrtf(fmaxf(dg, 1e-12f)) : 0.f;
}

// single-block exclusive scan of g_cnt -> g_off, init cursor
__global__ void k_scan(int N, int E) {
    __shared__ int part[1024];
    int t = threadIdx.x;
    int chunk = (N + 1023) / 1024;
    int b = t * chunk;
    int e = min(b + chunk, N);
    int s = 0;
    for (int i = b; i < e; i++) s += g_cnt[i];
    part[t] = s;
    __syncthreads();
    if (t == 0) {
        int run = 0;
        for (int i = 0; i < 1024; i++) { int tmp = part[i]; part[i] = run; run += tmp; }
        g_off[N] = E;
    }
    __syncthreads();
    int base = part[t];
    for (int i = b; i < e; i++) {
        g_off[i] = base;
        g_cursor[i] = base;
        base += g_cnt[i];
    }
}

__global__ void k_scatter(const int* __restrict__ ei,
                          const float* __restrict__ w, int E, int N) {
    int e = blockIdx.x * blockDim.x + threadIdx.x;
    if (e >= E) return;
    int s = clampi(ei[e], N);
    int d = clampi(ei[E + e], N);
    int pos = atomicAdd(&g_cursor[d], 1);
    if (pos < E) {
        g_csr_src[pos] = s;
        g_csr_norm[pos] = g_dinv[s] * w[e] * g_dinv[d];
    }
}

// ---------------- Y = A_norm @ X  (warp per node, float4 lanes) ----------------
__global__ void k_aggregate(const float* __restrict__ X, int N) {
    int warp = (blockIdx.x * blockDim.x + threadIdx.x) >> 5;
    int lane = threadIdx.x & 31;
    if (warp >= N) return;
    const float4* __restrict__ X4 = (const float4*)X;
    float di = g_dinv[warp];
    float sw = di * di;     // self-loop: dinv*1*dinv
    float4 x = X4[warp * 32 + lane];
    float4 acc = make_float4(x.x * sw, x.y * sw, x.z * sw, x.w * sw);
    int s0 = g_off[warp], s1 = g_off[warp + 1];
    for (int e = s0; e < s1; e++) {
        int s = g_csr_src[e];
        float w = g_csr_norm[e];
        float4 xs = X4[s * 32 + lane];
        acc.x = fmaf(xs.x, w, acc.x);
        acc.y = fmaf(xs.y, w, acc.y);
        acc.z = fmaf(xs.z, w, acc.z);
        acc.w = fmaf(xs.w, w, acc.w);
    }
    ((float4*)g_Y)[warp * 32 + lane] = acc;
}

// ---------------- fold weights: g_Wall[256][512], g_ball[512] ----------------
__global__ void k_weights(const float* __restrict__ Wc_i, const float* __restrict__ Wc_f,
                          const float* __restrict__ Wc_o,
                          const float* __restrict__ Wl_i, const float* __restrict__ Wl_f,
                          const float* __restrict__ Wl_o, const float* __restrict__ Wl_ct,
                          const float* __restrict__ bc_i, const float* __restrict__ bc_f,
                          const float* __restrict__ bc_o,
                          const float* __restrict__ bl_i, const float* __restrict__ bl_f,
                          const float* __restrict__ bl_o, const float* __restrict__ bl_ct) {
    int idx = blockIdx.x * blockDim.x + threadIdx.x;
    if (idx >= 256 * 512) return;
    int k = idx / 512, gj = idx % 512;
    int g = gj >> 7, j = gj & 127;
    const float* Wl = (g == 0) ? Wl_i : (g == 1) ? Wl_f : (g == 2) ? Wl_o : Wl_ct;
    float v;
    if (k < 128) {
        // reference bug kept: ct gate reuses conv_f -> g==3 uses Wc_f
        const float* Wc = (g == 0) ? Wc_i : (g == 2) ? Wc_o : Wc_f;
        float s = 0.f;
        #pragma unroll 8
        for (int t = 0; t < 128; t++) s = fmaf(Wc[k * 128 + t], Wl[t * 128 + j], s);
        v = s;
    } else {
        v = Wl[k * 128 + j];  // H part: rows 128..255 of Wl
    }
    g_Wall[k * 512 + gj] = v;
    if (k == 0) {
        const float* bc = (g == 0) ? bc_i : (g == 2) ? bc_o : bc_f;
        const float* bl = (g == 0) ? bl_i : (g == 1) ? bl_f : (g == 2) ? bl_o : bl_ct;
        float s = bl[j];
        #pragma unroll 8
        for (int t = 0; t < 128; t++) s = fmaf(bc[t], Wl[t * 128 + j], s);
        g_ball[gj] = s;
    }
}

// ---------------- GEMM: g_pre[N,512] = [Y | H][N,256] @ g_Wall + g_ball ----------------
#define BM 64
#define BN 64
#define BK 16
__global__ void k_gemm(const float* __restrict__ H, int N) {
    __shared__ float As[BK][BM + 4];
    __shared__ float Bs[BK][BN + 4];
    int tx = threadIdx.x & 15;
    int ty = threadIdx.x >> 4;
    int rowBase = blockIdx.y * BM;
    int colBase = blockIdx.x * BN;
    float acc[4][4] = {};
    for (int k0 = 0; k0 < 256; k0 += BK) {
        #pragma unroll
        for (int i = threadIdx.x; i < BM * BK; i += 256) {
            int r = i / BK, c = i % BK;
            int gr = rowBase + r, gk = k0 + c;
            float v = 0.f;
            if (gr < N) v = (gk < 128) ? g_Y[gr * 128 + gk] : H[gr * 128 + gk - 128];
            As[c][r] = v;
        }
        #pragma unroll
        for (int i = threadIdx.x; i < BK * BN; i += 256) {
            int r = i / BN, c = i % BN;
            Bs[r][c] = g_Wall[(k0 + r) * 512 + colBase + c];
        }
        __syncthreads();
        #pragma unroll
        for (int k = 0; k < BK; k++) {
            float a[4], b[4];
            #pragma unroll
            for (int i = 0; i < 4; i++) a[i] = As[k][ty * 4 + i];
            #pragma unroll
            for (int j = 0; j < 4; j++) b[j] = Bs[k][tx * 4 + j];
            #pragma unroll
            for (int i = 0; i < 4; i++)
                #pragma unroll
                for (int j = 0; j < 4; j++)
                    acc[i][j] = fmaf(a[i], b[j], acc[i][j]);
        }
        __syncthreads();
    }
    #pragma unroll
    for (int i = 0; i < 4; i++) {
        int gr = rowBase + ty * 4 + i;
        if (gr >= N) continue;
        #pragma unroll
        for (int j = 0; j < 4; j++) {
            int gc = colBase + tx * 4 + j;
            g_pre[gr * 512 + gc] = acc[i][j] + g_ball[gc];
        }
    }
}

// ---------------- epilogue: LSTM pointwise ----------------
__global__ void k_epilogue(const float* __restrict__ C, float* __restrict__ out, int N) {
    int idx = blockIdx.x * blockDim.x + threadIdx.x;
    if (idx >= N * FDIM) return;
    int n = idx >> 7, j = idx & 127;
    const float* p = g_pre + n * 512;
    float I  = 1.f / (1.f + __expf(-p[j]));
    float Fg = 1.f / (1.f + __expf(-p[128 + j]));
    float O  = 1.f / (1.f + __expf(-p[256 + j]));
    float Ct = tanhf(p[384 + j]);
    float Cn = Ct * I + Fg * C[idx];
    float Hn = O * tanhf(Cn);
    out[idx] = Hn;               // H_new
    out[N * FDIM + idx] = Cn;    // C_new
}

// ---------------- launch ----------------
extern "C" void kernel_launch(void* const* d_in, const int* in_sizes, int n_in,
                              void* d_out, int out_size) {
    const float* X  = (const float*)d_in[0];
    const int*   ei = (const int*)d_in[1];      // edge_index is int32 (JAX x64 disabled)
    const float* ew = (const float*)d_in[2];
    const float* H  = (const float*)d_in[3];
    const float* C  = (const float*)d_in[4];
    const float *Wc_i = (const float*)d_in[5],  *bc_i = (const float*)d_in[6],
                *Wl_i = (const float*)d_in[7],  *bl_i = (const float*)d_in[8];
    const float *Wc_f = (const float*)d_in[9],  *bc_f = (const float*)d_in[10],
                *Wl_f = (const float*)d_in[11], *bl_f = (const float*)d_in[12];
    const float *Wc_o = (const float*)d_in[13], *bc_o = (const float*)d_in[14],
                *Wl_o = (const float*)d_in[15], *bl_o = (const float*)d_in[16];
    const float *Wl_ct = (const float*)d_in[19], *bl_ct = (const float*)d_in[20];

    int N = in_sizes[0] / FDIM;
    int E = in_sizes[2];

    float* out = (float*)d_out;

    k_init<<<(N + 255) / 256, 256>>>(N);
    k_edge_deg<<<(E + 255) / 256, 256>>>(ei, ew, E, N);
    k_dinv<<<(N + 255) / 256, 256>>>(N);
    k_scan<<<1, 1024>>>(N, E);
    k_scatter<<<(E + 255) / 256, 256>>>(ei, ew, E, N);
    k_weights<<<(256 * 512 + 255) / 256, 256>>>(Wc_i, Wc_f, Wc_o,
                                                Wl_i, Wl_f, Wl_o, Wl_ct,
                                                bc_i, bc_f, bc_o,
                                                bl_i, bl_f, bl_o, bl_ct);
    k_aggregate<<<(N * 32 + 255) / 256, 256>>>(X, N);
    dim3 gg(512 / BN, (N + BM - 1) / BM);
    k_gemm<<<gg, 256>>>(H, N);
    k_epilogue<<<(N * FDIM + 255) / 256, 256>>>(C, out, N);
}

// round 4
// speedup vs baseline: 1.1858x; 1.1858x over previous
#include <cuda_runtime.h>
#include <cuda_bf16.h>
#include <math.h>
#include <stdint.h>

#define MAXN 10000
#define MAXE 640000
#define FDIM 128

// ---------------- device scratch (no allocation allowed) ----------------
__device__ __align__(16) float g_deg[MAXN];
__device__ __align__(16) float g_dinv[MAXN];
__device__ __align__(16) int   g_cnt[MAXN];
__device__ __align__(16) int   g_off[MAXN + 1];
__device__ __align__(16) int   g_cursor[MAXN];
__device__ __align__(16) int   g_csr_src[MAXE];
__device__ __align__(16) float g_csr_norm[MAXE];
__device__ __align__(16) float g_Y[MAXN * FDIM];
__device__ __align__(16) float g_Wall[256 * 512];   // [k][g*128+j]
__device__ __align__(16) float g_ball[512];
__device__ __align__(16) float g_pre[MAXN * 512];

__device__ __forceinline__ int clampi(int v, int n) {
    return v < 0 ? 0 : (v >= n ? n - 1 : v);
}

__device__ __forceinline__ uint32_t f2tf32(float f) {
    uint32_t r;
    asm("cvt.rna.tf32.f32 %0, %1;\n" : "=r"(r) : "f"(f));
    return r;
}

// ---------------- graph norm / CSR build ----------------
__global__ void k_init(int N) {
    int n = blockIdx.x * blockDim.x + threadIdx.x;
    if (n < N) { g_deg[n] = 1.0f; g_cnt[n] = 0; }   // self-loop weight 1
}

__global__ void k_edge_deg(const int* __restrict__ ei,
                           const float* __restrict__ w, int E, int N) {
    int e = blockIdx.x * blockDim.x + threadIdx.x;
    if (e >= E) return;
    int d = clampi(ei[E + e], N);
    atomicAdd(&g_deg[d], w[e]);
    atomicAdd(&g_cnt[d], 1);
}

__global__ void k_dinv(int N) {
    int n = blockIdx.x * blockDim.x + threadIdx.x;
    if (n >= N) return;
    float dg = g_deg[n];
    g_dinv[n] = dg > 0.f ? rsqrtf(fmaxf(dg, 1e-12f)) : 0.f;
}

// parallel exclusive scan of g_cnt -> g_off, init cursor (single block)
__global__ void k_scan(int N, int E) {
    __shared__ int part[1024];
    int t = threadIdx.x;
    int chunk = (N + 1023) / 1024;
    int b = t * chunk;
    int e = min(b + chunk, N);
    int s = 0;
    for (int i = b; i < e; i++) s += g_cnt[i];
    part[t] = s;
    __syncthreads();
    // Hillis-Steele inclusive scan over 1024 partials
    #pragma unroll
    for (int d = 1; d < 1024; d <<= 1) {
        int v = (t >= d) ? part[t - d] : 0;
        __syncthreads();
        part[t] += v;
        __syncthreads();
    }
    int base = (t == 0) ? 0 : part[t - 1];
    for (int i = b; i < e; i++) {
        g_off[i] = base;
        g_cursor[i] = base;
        base += g_cnt[i];
    }
    if (t == 0) g_off[N] = E;
}

__global__ void k_scatter(const int* __restrict__ ei,
                          const float* __restrict__ w, int E, int N) {
    int e = blockIdx.x * blockDim.x + threadIdx.x;
    if (e >= E) return;
    int s = clampi(ei[e], N);
    int d = clampi(ei[E + e], N);
    int pos = atomicAdd(&g_cursor[d], 1);
    if (pos < E) {
        g_csr_src[pos] = s;
        g_csr_norm[pos] = g_dinv[s] * w[e] * g_dinv[d];
    }
}

// ---------------- Y = A_norm @ X  (warp per node, float4 lanes) ----------------
__global__ void k_aggregate(const float* __restrict__ X, int N) {
    int warp = (blockIdx.x * blockDim.x + threadIdx.x) >> 5;
    int lane = threadIdx.x & 31;
    if (warp >= N) return;
    const float4* __restrict__ X4 = (const float4*)X;
    float di = g_dinv[warp];
    float sw = di * di;     // self-loop: dinv*1*dinv
    float4 x = X4[warp * 32 + lane];
    float4 acc = make_float4(x.x * sw, x.y * sw, x.z * sw, x.w * sw);
    int s0 = g_off[warp], s1 = g_off[warp + 1];
    for (int e = s0; e < s1; e++) {
        int s = g_csr_src[e];
        float w = g_csr_norm[e];
        float4 xs = X4[s * 32 + lane];
        acc.x = fmaf(xs.x, w, acc.x);
        acc.y = fmaf(xs.y, w, acc.y);
        acc.z = fmaf(xs.z, w, acc.z);
        acc.w = fmaf(xs.w, w, acc.w);
    }
    ((float4*)g_Y)[warp * 32 + lane] = acc;
}

// ---------------- fold weights: g_Wall[256][512], g_ball[512] ----------------
__global__ void k_weights(const float* __restrict__ Wc_i, const float* __restrict__ Wc_f,
                          const float* __restrict__ Wc_o,
                          const float* __restrict__ Wl_i, const float* __restrict__ Wl_f,
                          const float* __restrict__ Wl_o, const float* __restrict__ Wl_ct,
                          const float* __restrict__ bc_i, const float* __restrict__ bc_f,
                          const float* __restrict__ bc_o,
                          const float* __restrict__ bl_i, const float* __restrict__ bl_f,
                          const float* __restrict__ bl_o, const float* __restrict__ bl_ct) {
    int idx = blockIdx.x * blockDim.x + threadIdx.x;
    if (idx >= 256 * 512) return;
    int k = idx / 512, gj = idx % 512;
    int g = gj >> 7, j = gj & 127;
    const float* Wl = (g == 0) ? Wl_i : (g == 1) ? Wl_f : (g == 2) ? Wl_o : Wl_ct;
    float v;
    if (k < 128) {
        // reference bug kept: ct gate reuses conv_f -> g==3 uses Wc_f
        const float* Wc = (g == 0) ? Wc_i : (g == 2) ? Wc_o : Wc_f;
        float s = 0.f;
        #pragma unroll 8
        for (int t = 0; t < 128; t++) s = fmaf(Wc[k * 128 + t], Wl[t * 128 + j], s);
        v = s;
    } else {
        v = Wl[k * 128 + j];  // H part: rows 128..255 of Wl
    }
    g_Wall[k * 512 + gj] = v;
    if (k == 0) {
        const float* bc = (g == 0) ? bc_i : (g == 2) ? bc_o : bc_f;
        const float* bl = (g == 0) ? bl_i : (g == 1) ? bl_f : (g == 2) ? bl_o : bl_ct;
        float s = bl[j];
        #pragma unroll 8
        for (int t = 0; t < 128; t++) s = fmaf(bc[t], Wl[t * 128 + j], s);
        g_ball[gj] = s;
    }
}

// ---------------- tf32 tensor-core GEMM ----------------
// g_pre[N,512] = [Y | H][N,256] @ g_Wall + g_ball
// block: 256 thr (8 warps, 4Mx2N), tile 128x64, K-chunk 32
#define GM 128
#define GN 64
#define GK 32
#define GM_PAD (GM + 5)
#define GN_PAD (GN + 4)

__global__ __launch_bounds__(256) void k_gemm_tc(const float* __restrict__ H, int N) {
    __shared__ uint32_t As[GK][GM_PAD];   // tf32, [k][m]
    __shared__ uint32_t Bs[GK][GN_PAD];   // tf32, [k][n]

    int tid  = threadIdx.x;
    int wid  = tid >> 5;
    int lane = tid & 31;
    int warpM = wid & 3;          // 4 warps along M (32 rows each)
    int warpN = wid >> 2;         // 2 warps along N (32 cols each)
    int rowBase = blockIdx.y * GM;
    int colBase = blockIdx.x * GN;

    int grp = lane >> 2;          // 0..7
    int qid = lane & 3;           // 0..3

    float acc[2][4][4];
    #pragma unroll
    for (int i = 0; i < 2; i++)
        #pragma unroll
        for (int j = 0; j < 4; j++)
            #pragma unroll
            for (int t = 0; t < 4; t++) acc[i][j][t] = 0.f;

    for (int k0 = 0; k0 < 256; k0 += GK) {
        // A tile: 128 rows x 32 k. 4096 elems / 256 thr = 16 each.
        #pragma unroll
        for (int it = 0; it < 16; it++) {
            int i = tid + it * 256;
            int r = i >> 5, c = i & 31;       // r: 0..127, c: 0..31
            int gr = rowBase + r, gk = k0 + c;
            float v = 0.f;
            if (gr < N) v = (gk < 128) ? g_Y[gr * 128 + gk] : H[gr * 128 + gk - 128];
            As[c][r] = f2tf32(v);
        }
        // B tile: 32 k x 64 n. 2048 / 256 = 8 each.
        #pragma unroll
        for (int it = 0; it < 8; it++) {
            int i = tid + it * 256;
            int r = i >> 6, c = i & 63;
            Bs[r][c] = f2tf32(g_Wall[(k0 + r) * 512 + colBase + c]);
        }
        __syncthreads();

        #pragma unroll
        for (int kk = 0; kk < GK; kk += 8) {
            uint32_t a[2][4];
            #pragma unroll
            for (int mf = 0; mf < 2; mf++) {
                int row0 = warpM * 32 + mf * 16;
                a[mf][0] = As[kk + qid][row0 + grp];
                a[mf][1] = As[kk + qid][row0 + 8 + grp];
                a[mf][2] = As[kk + 4 + qid][row0 + grp];
                a[mf][3] = As[kk + 4 + qid][row0 + 8 + grp];
            }
            uint32_t b[4][2];
            #pragma unroll
            for (int nf = 0; nf < 4; nf++) {
                int col0 = warpN * 32 + nf * 8;
                b[nf][0] = Bs[kk + qid][col0 + grp];
                b[nf][1] = Bs[kk + 4 + qid][col0 + grp];
            }
            #pragma unroll
            for (int mf = 0; mf < 2; mf++)
                #pragma unroll
                for (int nf = 0; nf < 4; nf++) {
                    asm volatile(
                        "mma.sync.aligned.m16n8k8.row.col.f32.tf32.tf32.f32 "
                        "{%0,%1,%2,%3}, {%4,%5,%6,%7}, {%8,%9}, {%0,%1,%2,%3};\n"
                        : "+f"(acc[mf][nf][0]), "+f"(acc[mf][nf][1]),
                          "+f"(acc[mf][nf][2]), "+f"(acc[mf][nf][3])
                        : "r"(a[mf][0]), "r"(a[mf][1]), "r"(a[mf][2]), "r"(a[mf][3]),
                          "r"(b[nf][0]), "r"(b[nf][1]));
                }
        }
        __syncthreads();
    }

    // store: D frag layout: c0 (row=grp, col=qid*2), c1 (col+1), c2 (row+8), c3 (row+8,col+1)
    #pragma unroll
    for (int mf = 0; mf < 2; mf++) {
        #pragma unroll
        for (int nf = 0; nf < 4; nf++) {
            int row = rowBase + warpM * 32 + mf * 16 + grp;
            int col = colBase + warpN * 32 + nf * 8 + qid * 2;
            if (row < N) {
                g_pre[row * 512 + col]     = acc[mf][nf][0] + g_ball[col];
                g_pre[row * 512 + col + 1] = acc[mf][nf][1] + g_ball[col + 1];
            }
            if (row + 8 < N) {
                g_pre[(row + 8) * 512 + col]     = acc[mf][nf][2] + g_ball[col];
                g_pre[(row + 8) * 512 + col + 1] = acc[mf][nf][3] + g_ball[col + 1];
            }
        }
    }
}

// ---------------- epilogue: LSTM pointwise ----------------
__global__ void k_epilogue(const float* __restrict__ C, float* __restrict__ out, int N) {
    int idx = blockIdx.x * blockDim.x + threadIdx.x;
    if (idx >= N * FDIM) return;
    int n = idx >> 7, j = idx & 127;
    const float* p = g_pre + n * 512;
    float I  = 1.f / (1.f + __expf(-p[j]));
    float Fg = 1.f / (1.f + __expf(-p[128 + j]));
    float O  = 1.f / (1.f + __expf(-p[256 + j]));
    float Ct = tanhf(p[384 + j]);
    float Cn = Ct * I + Fg * C[idx];
    float Hn = O * tanhf(Cn);
    out[idx] = Hn;               // H_new
    out[N * FDIM + idx] = Cn;    // C_new
}

// ---------------- launch ----------------
extern "C" void kernel_launch(void* const* d_in, const int* in_sizes, int n_in,
                              void* d_out, int out_size) {
    const float* X  = (const float*)d_in[0];
    const int*   ei = (const int*)d_in[1];      // edge_index is int32 (JAX x64 disabled)
    const float* ew = (const float*)d_in[2];
    const float* H  = (const float*)d_in[3];
    const float* C  = (const float*)d_in[4];
    const float *Wc_i = (const float*)d_in[5],  *bc_i = (const float*)d_in[6],
                *Wl_i = (const float*)d_in[7],  *bl_i = (const float*)d_in[8];
    const float *Wc_f = (const float*)d_in[9],  *bc_f = (const float*)d_in[10],
                *Wl_f = (const float*)d_in[11], *bl_f = (const float*)d_in[12];
    const float *Wc_o = (const float*)d_in[13], *bc_o = (const float*)d_in[14],
                *Wl_o = (const float*)d_in[15], *bl_o = (const float*)d_in[16];
    const float *Wl_ct = (const float*)d_in[19], *bl_ct = (const float*)d_in[20];

    int N = in_sizes[0] / FDIM;
    int E = in_sizes[2];

    float* out = (float*)d_out;

    k_init<<<(N + 255) / 256, 256>>>(N);
    k_edge_deg<<<(E + 255) / 256, 256>>>(ei, ew, E, N);
    k_dinv<<<(N + 255) / 256, 256>>>(N);
    k_scan<<<1, 1024>>>(N, E);
    k_scatter<<<(E + 255) / 256, 256>>>(ei, ew, E, N);
    k_weights<<<(256 * 512 + 255) / 256, 256>>>(Wc_i, Wc_f, Wc_o,
                                                Wl_i, Wl_f, Wl_o, Wl_ct,
                                                bc_i, bc_f, bc_o,
                                                bl_i, bl_f, bl_o, bl_ct);
    k_aggregate<<<(N * 32 + 255) / 256, 256>>>(X, N);
    dim3 gg(512 / GN, (N + GM - 1) / GM);
    k_gemm_tc<<<gg, 256>>>(H, N);
    k_epilogue<<<(N * FDIM + 255) / 256, 256>>>(C, out, N);
}

// round 5
// speedup vs baseline: 1.7928x; 1.5119x over previous
#include <cuda_runtime.h>
#include <cuda_bf16.h>
#include <math.h>
#include <stdint.h>

#define MAXN 10000
#define MAXE 640000
#define FDIM 128

// ---------------- device scratch (no allocation allowed) ----------------
__device__ __align__(16) float g_deg[MAXN];
__device__ __align__(16) float g_dinv[MAXN];
__device__ __align__(16) int   g_cnt[MAXN];
__device__ __align__(16) int   g_off[MAXN + 1];
__device__ __align__(16) int   g_cursor[MAXN];
__device__ __align__(16) int   g_csr_src[MAXE];
__device__ __align__(16) float g_csr_norm[MAXE];
__device__ __align__(16) float g_Y[MAXN * FDIM];
__device__ __align__(16) float g_Wall[256 * 512];   // [k][g*128+j]
__device__ __align__(16) float g_ball[512];
__device__ __align__(16) float g_pre[MAXN * 512];

__device__ __forceinline__ int clampi(int v, int n) {
    return v < 0 ? 0 : (v >= n ? n - 1 : v);
}

__device__ __forceinline__ uint32_t f2tf32(float f) {
    uint32_t r;
    asm("cvt.rna.tf32.f32 %0, %1;\n" : "=r"(r) : "f"(f));
    return r;
}

// ---------------- stage 1: init ----------------
__global__ void k_init(int N) {
    int n = blockIdx.x * blockDim.x + threadIdx.x;
    if (n < N) { g_deg[n] = 1.0f; g_cnt[n] = 0; }   // self-loop weight 1
}

// ---------------- stage 2: degree + count ----------------
__global__ void k_edge_deg(const int* __restrict__ ei,
                           const float* __restrict__ w, int E, int N) {
    int e = blockIdx.x * blockDim.x + threadIdx.x;
    if (e >= E) return;
    int d = clampi(ei[E + e], N);
    atomicAdd(&g_deg[d], w[e]);
    atomicAdd(&g_cnt[d], 1);
}

// ---------------- stage 3 (fused): scan | dinv | weight-fold | copy | bias ----------------
// block 0        : shuffle-based exclusive scan of g_cnt -> g_off/g_cursor
// blocks 1..10   : dinv
// blocks 11..74  : 4 gates x 16 tiles of (WcWl) 32x32 output, K=128
// blocks 75..90  : copy Wl bottom half (rows 128..255) into g_Wall
// block 91       : bias fold g_ball
__global__ __launch_bounds__(1024) void k_mid(
    const float* __restrict__ Wc_i, const float* __restrict__ Wc_f,
    const float* __restrict__ Wc_o,
    const float* __restrict__ Wl_i, const float* __restrict__ Wl_f,
    const float* __restrict__ Wl_o, const float* __restrict__ Wl_ct,
    const float* __restrict__ bc_i, const float* __restrict__ bc_f,
    const float* __restrict__ bc_o,
    const float* __restrict__ bl_i, const float* __restrict__ bl_f,
    const float* __restrict__ bl_o, const float* __restrict__ bl_ct,
    int N, int E)
{
    __shared__ float As[32][128];
    __shared__ float Bs[128][32];
    __shared__ int wsum[32];
    int b = blockIdx.x, t = threadIdx.x;

    if (b == 0) {
        // ---- scan ----
        int lane = t & 31, w5 = t >> 5;
        int chunk = (N + 1023) >> 10;                 // <=16 for N<=16384
        int bgn = t * chunk;
        int end = min(bgn + chunk, N);
        int m = end > bgn ? end - bgn : 0;
        int cnt[16];
        int s = 0;
        #pragma unroll
        for (int i = 0; i < 16; i++) {
            if (i < m) { cnt[i] = g_cnt[bgn + i]; s += cnt[i]; }
        }
        int incl = s;
        #pragma unroll
        for (int d = 1; d < 32; d <<= 1) {
            int v = __shfl_up_sync(0xffffffffu, incl, d);
            if (lane >= d) incl += v;
        }
        if (lane == 31) wsum[w5] = incl;
        __syncthreads();
        if (w5 == 0) {
            int v = wsum[lane];
            int iv = v;
            #pragma unroll
            for (int d = 1; d < 32; d <<= 1) {
                int u = __shfl_up_sync(0xffffffffu, iv, d);
                if (lane >= d) iv += u;
            }
            wsum[lane] = iv - v;                       // exclusive warp offset
        }
        __syncthreads();
        int base = wsum[w5] + (incl - s);
        #pragma unroll
        for (int i = 0; i < 16; i++) {
            if (i < m) {
                g_off[bgn + i] = base;
                g_cursor[bgn + i] = base;
                base += cnt[i];
            }
        }
        if (t == 0) g_off[N] = E;
    } else if (b < 11) {
        // ---- dinv ----
        int n = (b - 1) * 1024 + t;
        if (n < N) {
            float dg = g_deg[n];
            g_dinv[n] = dg > 0.f ? rsqrtf(fmaxf(dg, 1e-12f)) : 0.f;
        }
    } else if (b < 75) {
        // ---- tiled weight fold: g_Wall[0..127][g*128+j] = Wc_g @ Wl_g(top) ----
        int z = b - 11;
        int g = z >> 4, tile = z & 15;
        int tr = tile >> 2, tc = tile & 3;
        // reference bug kept: ct gate reuses conv_f
        const float* Wc = (g == 0) ? Wc_i : (g == 2) ? Wc_o : Wc_f;
        const float* Wl = (g == 0) ? Wl_i : (g == 1) ? Wl_f : (g == 2) ? Wl_o : Wl_ct;
        #pragma unroll
        for (int it = 0; it < 4; it++) {
            int i = t + it * 1024;
            int r = i >> 7, k = i & 127;
            As[r][k] = Wc[(tr * 32 + r) * 128 + k];
        }
        #pragma unroll
        for (int it = 0; it < 4; it++) {
            int i = t + it * 1024;
            int k = i >> 5, c = i & 31;
            Bs[k][c] = Wl[k * 128 + tc * 32 + c];
        }
        __syncthreads();
        int r = t >> 5, c = t & 31;
        float acc = 0.f;
        #pragma unroll 16
        for (int k = 0; k < 128; k++) acc = fmaf(As[r][k], Bs[k][c], acc);
        g_Wall[(tr * 32 + r) * 512 + g * 128 + tc * 32 + c] = acc;
    } else if (b < 91) {
        // ---- copy Wl bottom half: g_Wall[128+r][g*128+j] = Wl_g[128+r][j] ----
        int fid = (b - 75) * 1024 + t;                 // 0..16383 float4s
        int r2 = fid >> 7, c4 = fid & 127;
        int g = c4 >> 5, j4 = c4 & 31;
        const float* Wl = (g == 0) ? Wl_i : (g == 1) ? Wl_f : (g == 2) ? Wl_o : Wl_ct;
        float4 v = *(const float4*)&Wl[(128 + r2) * 128 + j4 * 4];
        *(float4*)&g_Wall[(128 + r2) * 512 + g * 128 + j4 * 4] = v;
    } else {
        // ---- bias fold ----
        if (t < 512) {
            int g = t >> 7, j = t & 127;
            const float* Wl = (g == 0) ? Wl_i : (g == 1) ? Wl_f : (g == 2) ? Wl_o : Wl_ct;
            const float* bc = (g == 0) ? bc_i : (g == 2) ? bc_o : bc_f;
            const float* bl = (g == 0) ? bl_i : (g == 1) ? bl_f : (g == 2) ? bl_o : bl_ct;
            float s = bl[j];
            #pragma unroll 16
            for (int k = 0; k < 128; k++) s = fmaf(bc[k], Wl[k * 128 + j], s);
            g_ball[t] = s;
        }
    }
}

// ---------------- stage 4: CSR scatter ----------------
__global__ void k_scatter(const int* __restrict__ ei,
                          const float* __restrict__ w, int E, int N) {
    int e = blockIdx.x * blockDim.x + threadIdx.x;
    if (e >= E) return;
    int s = clampi(ei[e], N);
    int d = clampi(ei[E + e], N);
    int pos = atomicAdd(&g_cursor[d], 1);
    if (pos < E) {
        g_csr_src[pos] = s;
        g_csr_norm[pos] = g_dinv[s] * w[e] * g_dinv[d];
    }
}

// ---------------- stage 5: Y = A_norm @ X (warp per node) ----------------
__global__ void k_aggregate(const float* __restrict__ X, int N) {
    int warp = (blockIdx.x * blockDim.x + threadIdx.x) >> 5;
    int lane = threadIdx.x & 31;
    if (warp >= N) return;
    const float4* __restrict__ X4 = (const float4*)X;
    float di = g_dinv[warp];
    float sw = di * di;     // self-loop: dinv*1*dinv
    float4 x = X4[warp * 32 + lane];
    float4 acc = make_float4(x.x * sw, x.y * sw, x.z * sw, x.w * sw);
    int s0 = g_off[warp], s1 = g_off[warp + 1];
    for (int e = s0; e < s1; e++) {
        int s = g_csr_src[e];
        float w = g_csr_norm[e];
        float4 xs = X4[s * 32 + lane];
        acc.x = fmaf(xs.x, w, acc.x);
        acc.y = fmaf(xs.y, w, acc.y);
        acc.z = fmaf(xs.z, w, acc.z);
        acc.w = fmaf(xs.w, w, acc.w);
    }
    ((float4*)g_Y)[warp * 32 + lane] = acc;
}

// ---------------- stage 6: tf32 tensor-core GEMM ----------------
// g_pre[N,512] = [Y | H][N,256] @ g_Wall + g_ball
#define GM 128
#define GN 64
#define GK 32
#define GM_PAD (GM + 5)
#define GN_PAD (GN + 4)

__global__ __launch_bounds__(256) void k_gemm_tc(const float* __restrict__ H, int N) {
    __shared__ uint32_t As[GK][GM_PAD];   // tf32, [k][m]
    __shared__ uint32_t Bs[GK][GN_PAD];   // tf32, [k][n]

    int tid  = threadIdx.x;
    int wid  = tid >> 5;
    int lane = tid & 31;
    int warpM = wid & 3;
    int warpN = wid >> 2;
    int rowBase = blockIdx.y * GM;
    int colBase = blockIdx.x * GN;

    int grp = lane >> 2;
    int qid = lane & 3;

    // A-tile addressing (float4): i = tid + it*256, it<8 -> r=i>>3 (0..127), c4=i&7
    int a_r  = tid >> 3, a_c4 = tid & 7;
    // B-tile addressing (float4): it<2 -> r=i>>4 (0..31), c4=i&15
    int b_r  = tid >> 4, b_c4 = tid & 15;

    float4 aPf[2], bPf_0, bPf_1;   // prefetch regs (A: 2 rows x f4; B: 2 f4)

    // ---- load K-tile k0 into prefetch regs ----
    auto loadA = [&](int k0, float4* dst) {
        const float* src = (k0 < 128) ? g_Y : H;
        int koff = (k0 < 128) ? k0 : k0 - 128;
        #pragma unroll
        for (int it = 0; it < 2; it++) {
            int r = a_r + it * 32 + ((it) ? 0 : 0);    // rows a_r and a_r+32? see below
            (void)r;
        }
    };
    (void)loadA;

    // Explicit prefetch: 8 float4 A loads would need 8 regs sets; instead each
    // thread handles 4 A-float4 (it=0..3 over 1024 f4) and 2 B-float4.
    float4 aReg[4];
    float4 bReg[2];

    #define LOAD_A_REG(k0)                                                        \
        {                                                                         \
            const float* _src = ((k0) < 128) ? g_Y : H;                           \
            int _koff = ((k0) < 128) ? (k0) : (k0) - 128;                         \
            _Pragma("unroll")                                                     \
            for (int it = 0; it < 4; it++) {                                      \
                int i = tid + it * 256;                                           \
                int r = i >> 3, c4 = i & 7;                                       \
                int gr = rowBase + r;                                             \
                aReg[it] = (gr < N)                                               \
                    ? *(const float4*)&_src[gr * 128 + _koff + c4 * 4]            \
                    : make_float4(0.f, 0.f, 0.f, 0.f);                            \
            }                                                                     \
        }
    #define LOAD_B_REG(k0)                                                        \
        {                                                                         \
            _Pragma("unroll")                                                     \
            for (int it = 0; it < 2; it++) {                                      \
                int i = tid + it * 256;                                           \
                int r = i >> 4, c4 = i & 15;                                      \
                bReg[it] = *(const float4*)&g_Wall[((k0) + r) * 512 + colBase + c4 * 4]; \
            }                                                                     \
        }
    #define STORE_TILES()                                                         \
        {                                                                         \
            _Pragma("unroll")                                                     \
            for (int it = 0; it < 4; it++) {                                      \
                int i = tid + it * 256;                                           \
                int r = i >> 3, c4 = i & 7;                                       \
                As[c4 * 4 + 0][r] = f2tf32(aReg[it].x);                           \
                As[c4 * 4 + 1][r] = f2tf32(aReg[it].y);                           \
                As[c4 * 4 + 2][r] = f2tf32(aReg[it].z);                           \
                As[c4 * 4 + 3][r] = f2tf32(aReg[it].w);                           \
            }                                                                     \
            _Pragma("unroll")                                                     \
            for (int it = 0; it < 2; it++) {                                      \
                int i = tid + it * 256;                                           \
                int r = i >> 4, c4 = i & 15;                                      \
                Bs[r][c4 * 4 + 0] = f2tf32(bReg[it].x);                           \
                Bs[r][c4 * 4 + 1] = f2tf32(bReg[it].y);                           \
                Bs[r][c4 * 4 + 2] = f2tf32(bReg[it].z);                           \
                Bs[r][c4 * 4 + 3] = f2tf32(bReg[it].w);                           \
            }                                                                     \
        }

    float acc[2][4][4];
    #pragma unroll
    for (int i = 0; i < 2; i++)
        #pragma unroll
        for (int j = 0; j < 4; j++)
            #pragma unroll
            for (int t2 = 0; t2 < 4; t2++) acc[i][j][t2] = 0.f;

    LOAD_A_REG(0); LOAD_B_REG(0);
    STORE_TILES();
    __syncthreads();

    for (int k0 = 0; k0 < 256; k0 += GK) {
        int kn = k0 + GK;
        if (kn < 256) { LOAD_A_REG(kn); LOAD_B_REG(kn); }

        #pragma unroll
        for (int kk = 0; kk < GK; kk += 8) {
            uint32_t a[2][4];
            #pragma unroll
            for (int mf = 0; mf < 2; mf++) {
                int row0 = warpM * 32 + mf * 16;
                a[mf][0] = As[kk + qid][row0 + grp];
                a[mf][1] = As[kk + qid][row0 + 8 + grp];
                a[mf][2] = As[kk + 4 + qid][row0 + grp];
                a[mf][3] = As[kk + 4 + qid][row0 + 8 + grp];
            }
            uint32_t bf[4][2];
            #pragma unroll
            for (int nf = 0; nf < 4; nf++) {
                int col0 = warpN * 32 + nf * 8;
                bf[nf][0] = Bs[kk + qid][col0 + grp];
                bf[nf][1] = Bs[kk + 4 + qid][col0 + grp];
            }
            #pragma unroll
            for (int mf = 0; mf < 2; mf++)
                #pragma unroll
                for (int nf = 0; nf < 4; nf++) {
                    asm volatile(
                        "mma.sync.aligned.m16n8k8.row.col.f32.tf32.tf32.f32 "
                        "{%0,%1,%2,%3}, {%4,%5,%6,%7}, {%8,%9}, {%0,%1,%2,%3};\n"
                        : "+f"(acc[mf][nf][0]), "+f"(acc[mf][nf][1]),
                          "+f"(acc[mf][nf][2]), "+f"(acc[mf][nf][3])
                        : "r"(a[mf][0]), "r"(a[mf][1]), "r"(a[mf][2]), "r"(a[mf][3]),
                          "r"(bf[nf][0]), "r"(bf[nf][1]));
                }
        }
        __syncthreads();
        if (kn < 256) {
            STORE_TILES();
            __syncthreads();
        }
    }

    #pragma unroll
    for (int mf = 0; mf < 2; mf++) {
        #pragma unroll
        for (int nf = 0; nf < 4; nf++) {
            int row = rowBase + warpM * 32 + mf * 16 + grp;
            int col = colBase + warpN * 32 + nf * 8 + qid * 2;
            if (row < N) {
                g_pre[row * 512 + col]     = acc[mf][nf][0] + g_ball[col];
                g_pre[row * 512 + col + 1] = acc[mf][nf][1] + g_ball[col + 1];
            }
            if (row + 8 < N) {
                g_pre[(row + 8) * 512 + col]     = acc[mf][nf][2] + g_ball[col];
                g_pre[(row + 8) * 512 + col + 1] = acc[mf][nf][3] + g_ball[col + 1];
            }
        }
    }
}

// ---------------- stage 7: LSTM pointwise epilogue ----------------
__global__ void k_epilogue(const float* __restrict__ C, float* __restrict__ out, int N) {
    int idx = blockIdx.x * blockDim.x + threadIdx.x;
    if (idx >= N * FDIM) return;
    int n = idx >> 7, j = idx & 127;
    const float* p = g_pre + n * 512;
    float I  = 1.f / (1.f + __expf(-p[j]));
    float Fg = 1.f / (1.f + __expf(-p[128 + j]));
    float O  = 1.f / (1.f + __expf(-p[256 + j]));
    float Ct = tanhf(p[384 + j]);
    float Cn = Ct * I + Fg * C[idx];
    float Hn = O * tanhf(Cn);
    out[idx] = Hn;               // H_new
    out[N * FDIM + idx] = Cn;    // C_new
}

// ---------------- launch ----------------
extern "C" void kernel_launch(void* const* d_in, const int* in_sizes, int n_in,
                              void* d_out, int out_size) {
    const float* X  = (const float*)d_in[0];
    const int*   ei = (const int*)d_in[1];      // edge_index is int32 (JAX x64 disabled)
    const float* ew = (const float*)d_in[2];
    const float* H  = (const float*)d_in[3];
    const float* C  = (const float*)d_in[4];
    const float *Wc_i = (const float*)d_in[5],  *bc_i = (const float*)d_in[6],
                *Wl_i = (const float*)d_in[7],  *bl_i = (const float*)d_in[8];
    const float *Wc_f = (const float*)d_in[9],  *bc_f = (const float*)d_in[10],
                *Wl_f = (const float*)d_in[11], *bl_f = (const float*)d_in[12];
    const float *Wc_o = (const float*)d_in[13], *bc_o = (const float*)d_in[14],
                *Wl_o = (const float*)d_in[15], *bl_o = (const float*)d_in[16];
    const float *Wl_ct = (const float*)d_in[19], *bl_ct = (const float*)d_in[20];

    int N = in_sizes[0] / FDIM;
    int E = in_sizes[2];

    float* out = (float*)d_out;

    k_init<<<(N + 255) / 256, 256>>>(N);
    k_edge_deg<<<(E + 255) / 256, 256>>>(ei, ew, E, N);
    k_mid<<<92, 1024>>>(Wc_i, Wc_f, Wc_o,
                        Wl_i, Wl_f, Wl_o, Wl_ct,
                        bc_i, bc_f, bc_o,
                        bl_i, bl_f, bl_o, bl_ct, N, E);
    k_scatter<<<(E + 255) / 256, 256>>>(ei, ew, E, N);
    k_aggregate<<<(N * 32 + 255) / 256, 256>>>(X, N);
    dim3 gg(512 / GN, (N + GM - 1) / GM);
    k_gemm_tc<<<gg, 256>>>(H, N);
    k_epilogue<<<(N * FDIM + 255) / 256, 256>>>(C, out, N);
}

// round 6
// speedup vs baseline: 1.8714x; 1.0439x over previous
#include <cuda_runtime.h>
#include <cuda_bf16.h>
#include <math.h>
#include <stdint.h>

#define MAXN 10000
#define MAXE 640000
#define FDIM 128

// ---------------- device scratch (no allocation allowed) ----------------
__device__ __align__(16) unsigned long long g_pk[MAXN];  // [w_fixed<<20 | cnt]
__device__ __align__(16) float g_dinv[MAXN];
__device__ __align__(16) int   g_off[MAXN + 1];
__device__ __align__(16) int   g_cursor[MAXN];
__device__ __align__(16) int2  g_csr[MAXE];              // (src, w*dinv[src])
__device__ __align__(16) float g_Y[MAXN * FDIM];
__device__ __align__(16) float g_Wall[256 * 512];        // [k][g*128+j]
__device__ __align__(16) float g_ball[512];
__device__ __align__(16) float g_pre[MAXN * 512];

__device__ __forceinline__ int clampi(int v, int n) {
    return v < 0 ? 0 : (v >= n ? n - 1 : v);
}

__device__ __forceinline__ uint32_t f2tf32(float f) {
    uint32_t r;
    asm("cvt.rna.tf32.f32 %0, %1;\n" : "=r"(r) : "f"(f));
    return r;
}

// ---------------- stage 1: init ----------------
__global__ void k_init(int N) {
    int n = blockIdx.x * blockDim.x + threadIdx.x;
    if (n < N) g_pk[n] = 0ull;
}

// ---------------- stage 2: packed degree+count (one 64b atomic per edge) ----------------
__global__ void k_edge_deg(const int* __restrict__ ei,
                           const float* __restrict__ w, int E, int N) {
    int e = blockIdx.x * blockDim.x + threadIdx.x;
    if (e >= E) return;
    int d = clampi(ei[E + e], N);
    unsigned int wf = __float2uint_rn(w[e] * 1048576.0f);   // 2^20 fixed point
    unsigned long long add = ((unsigned long long)wf << 20) | 1ull;
    atomicAdd(&g_pk[d], add);
}

// ---------------- stage 3a: scan + dinv (11 blocks) ----------------
__global__ __launch_bounds__(1024) void k_midA(int N, int E) {
    __shared__ int wsum[32];
    int b = blockIdx.x, t = threadIdx.x;
    if (b == 0) {
        // shuffle-based exclusive scan of counts -> g_off/g_cursor
        int lane = t & 31, w5 = t >> 5;
        int chunk = (N + 1023) >> 10;                  // <=16
        int bgn = t * chunk;
        int end = min(bgn + chunk, N);
        int m = end > bgn ? end - bgn : 0;
        int cnt[16];
        int s = 0;
        #pragma unroll
        for (int i = 0; i < 16; i++) {
            if (i < m) { cnt[i] = (int)(g_pk[bgn + i] & 0xFFFFFull); s += cnt[i]; }
        }
        int incl = s;
        #pragma unroll
        for (int d = 1; d < 32; d <<= 1) {
            int v = __shfl_up_sync(0xffffffffu, incl, d);
            if (lane >= d) incl += v;
        }
        if (lane == 31) wsum[w5] = incl;
        __syncthreads();
        if (w5 == 0) {
            int v = wsum[lane];
            int iv = v;
            #pragma unroll
            for (int d = 1; d < 32; d <<= 1) {
                int u = __shfl_up_sync(0xffffffffu, iv, d);
                if (lane >= d) iv += u;
            }
            wsum[lane] = iv - v;
        }
        __syncthreads();
        int base = wsum[w5] + (incl - s);
        #pragma unroll
        for (int i = 0; i < 16; i++) {
            if (i < m) {
                g_off[bgn + i] = base;
                g_cursor[bgn + i] = base;
                base += cnt[i];
            }
        }
        if (t == 0) g_off[N] = E;
    } else {
        int n = (b - 1) * 1024 + t;
        if (n < N) {
            unsigned long long pk = g_pk[n];
            float dg = 1.0f + (float)((double)(pk >> 20) * (1.0 / 1048576.0));
            g_dinv[n] = dg > 0.f ? rsqrtf(fmaxf(dg, 1e-12f)) : 0.f;
        }
    }
}

// ---------------- stage 3b (parallel branch): weight fold / copy / bias ----------------
// blocks 0..63  : 4 gates x 16 tiles of (Wc@Wl_top) 32x32, K=128
// blocks 64..79 : copy Wl bottom half into g_Wall
// block 80      : bias fold
__global__ __launch_bounds__(1024) void k_weights(
    const float* __restrict__ Wc_i, const float* __restrict__ Wc_f,
    const float* __restrict__ Wc_o,
    const float* __restrict__ Wl_i, const float* __restrict__ Wl_f,
    const float* __restrict__ Wl_o, const float* __restrict__ Wl_ct,
    const float* __restrict__ bc_i, const float* __restrict__ bc_f,
    const float* __restrict__ bc_o,
    const float* __restrict__ bl_i, const float* __restrict__ bl_f,
    const float* __restrict__ bl_o, const float* __restrict__ bl_ct)
{
    __shared__ float As[32][128];
    __shared__ float Bs[128][32];
    int b = blockIdx.x, t = threadIdx.x;
    if (b < 64) {
        int g = b >> 4, tile = b & 15;
        int tr = tile >> 2, tc = tile & 3;
        // reference bug kept: ct gate reuses conv_f
        const float* Wc = (g == 0) ? Wc_i : (g == 2) ? Wc_o : Wc_f;
        const float* Wl = (g == 0) ? Wl_i : (g == 1) ? Wl_f : (g == 2) ? Wl_o : Wl_ct;
        #pragma unroll
        for (int it = 0; it < 4; it++) {
            int i = t + it * 1024;
            int r = i >> 7, k = i & 127;
            As[r][k] = Wc[(tr * 32 + r) * 128 + k];
        }
        #pragma unroll
        for (int it = 0; it < 4; it++) {
            int i = t + it * 1024;
            int k = i >> 5, c = i & 31;
            Bs[k][c] = Wl[k * 128 + tc * 32 + c];
        }
        __syncthreads();
        int r = t >> 5, c = t & 31;
        float acc = 0.f;
        #pragma unroll 16
        for (int k = 0; k < 128; k++) acc = fmaf(As[r][k], Bs[k][c], acc);
        g_Wall[(tr * 32 + r) * 512 + g * 128 + tc * 32 + c] = acc;
    } else if (b < 80) {
        int fid = (b - 64) * 1024 + t;                 // 0..16383 float4s
        int r2 = fid >> 7, c4 = fid & 127;
        int g = c4 >> 5, j4 = c4 & 31;
        const float* Wl = (g == 0) ? Wl_i : (g == 1) ? Wl_f : (g == 2) ? Wl_o : Wl_ct;
        float4 v = *(const float4*)&Wl[(128 + r2) * 128 + j4 * 4];
        *(float4*)&g_Wall[(128 + r2) * 512 + g * 128 + j4 * 4] = v;
    } else {
        if (t < 512) {
            int g = t >> 7, j = t & 127;
            const float* Wl = (g == 0) ? Wl_i : (g == 1) ? Wl_f : (g == 2) ? Wl_o : Wl_ct;
            const float* bc = (g == 0) ? bc_i : (g == 2) ? bc_o : bc_f;
            const float* bl = (g == 0) ? bl_i : (g == 1) ? bl_f : (g == 2) ? bl_o : bl_ct;
            float s = bl[j];
            #pragma unroll 16
            for (int k = 0; k < 128; k++) s = fmaf(bc[k], Wl[k * 128 + j], s);
            g_ball[t] = s;
        }
    }
}

// ---------------- stage 4: CSR scatter (packed 8B store, no dinv[d]) ----------------
__global__ void k_scatter(const int* __restrict__ ei,
                          const float* __restrict__ w, int E, int N) {
    int e = blockIdx.x * blockDim.x + threadIdx.x;
    if (e >= E) return;
    int s = clampi(ei[e], N);
    int d = clampi(ei[E + e], N);
    int pos = atomicAdd(&g_cursor[d], 1);
    if (pos < E) {
        float nrm = w[e] * g_dinv[s];                  // dinv[d] applied in aggregate
        g_csr[pos] = make_int2(s, __float_as_int(nrm));
    }
}

// ---------------- stage 5: Y = A_norm @ X (warp per node) ----------------
__global__ void k_aggregate(const float* __restrict__ X, int N) {
    int warp = (blockIdx.x * blockDim.x + threadIdx.x) >> 5;
    int lane = threadIdx.x & 31;
    if (warp >= N) return;
    const float4* __restrict__ X4 = (const float4*)X;
    float di = g_dinv[warp];
    // self loop: dinv[d]*1*dinv[d]*X[d]; one dinv factor applied at the end
    float4 x = X4[warp * 32 + lane];
    float4 acc = make_float4(x.x * di, x.y * di, x.z * di, x.w * di);
    int s0 = g_off[warp], s1 = g_off[warp + 1];
    for (int e = s0; e < s1; e++) {
        int2 ed = __ldg(&g_csr[e]);
        float w = __int_as_float(ed.y);
        float4 xs = X4[ed.x * 32 + lane];
        acc.x = fmaf(xs.x, w, acc.x);
        acc.y = fmaf(xs.y, w, acc.y);
        acc.z = fmaf(xs.z, w, acc.z);
        acc.w = fmaf(xs.w, w, acc.w);
    }
    acc.x *= di; acc.y *= di; acc.z *= di; acc.w *= di;
    ((float4*)g_Y)[warp * 32 + lane] = acc;
}

// ---------------- stage 6: tf32 tensor-core GEMM ----------------
// g_pre[N,512] = [Y | H][N,256] @ g_Wall + g_ball
#define GM 128
#define GN 64
#define GK 32
#define GM_PAD (GM + 5)
#define GN_PAD (GN + 4)

__global__ __launch_bounds__(256) void k_gemm_tc(const float* __restrict__ H, int N) {
    __shared__ uint32_t As[GK][GM_PAD];   // tf32, [k][m]
    __shared__ uint32_t Bs[GK][GN_PAD];   // tf32, [k][n]

    int tid  = threadIdx.x;
    int wid  = tid >> 5;
    int lane = tid & 31;
    int warpM = wid & 3;
    int warpN = wid >> 2;
    int rowBase = blockIdx.y * GM;
    int colBase = blockIdx.x * GN;

    int grp = lane >> 2;
    int qid = lane & 3;

    float4 aReg[4];
    float4 bReg[2];

    #define LOAD_A_REG(k0)                                                        \
        {                                                                         \
            const float* _src = ((k0) < 128) ? g_Y : H;                           \
            int _koff = ((k0) < 128) ? (k0) : (k0) - 128;                         \
            _Pragma("unroll")                                                     \
            for (int it = 0; it < 4; it++) {                                      \
                int i = tid + it * 256;                                           \
                int r = i >> 3, c4 = i & 7;                                       \
                int gr = rowBase + r;                                             \
                aReg[it] = (gr < N)                                               \
                    ? *(const float4*)&_src[gr * 128 + _koff + c4 * 4]            \
                    : make_float4(0.f, 0.f, 0.f, 0.f);                            \
            }                                                                     \
        }
    #define LOAD_B_REG(k0)                                                        \
        {                                                                         \
            _Pragma("unroll")                                                     \
            for (int it = 0; it < 2; it++) {                                      \
                int i = tid + it * 256;                                           \
                int r = i >> 4, c4 = i & 15;                                      \
                bReg[it] = *(const float4*)&g_Wall[((k0) + r) * 512 + colBase + c4 * 4]; \
            }                                                                     \
        }
    #define STORE_TILES()                                                         \
        {                                                                         \
            _Pragma("unroll")                                                     \
            for (int it = 0; it < 4; it++) {                                      \
                int i = tid + it * 256;                                           \
                int r = i >> 3, c4 = i & 7;                                       \
                As[c4 * 4 + 0][r] = f2tf32(aReg[it].x);                           \
                As[c4 * 4 + 1][r] = f2tf32(aReg[it].y);                           \
                As[c4 * 4 + 2][r] = f2tf32(aReg[it].z);                           \
                As[c4 * 4 + 3][r] = f2tf32(aReg[it].w);                           \
            }                                                                     \
            _Pragma("unroll")                                                     \
            for (int it = 0; it < 2; it++) {                                      \
                int i = tid + it * 256;                                           \
                int r = i >> 4, c4 = i & 15;                                      \
                Bs[r][c4 * 4 + 0] = f2tf32(bReg[it].x);                           \
                Bs[r][c4 * 4 + 1] = f2tf32(bReg[it].y);                           \
                Bs[r][c4 * 4 + 2] = f2tf32(bReg[it].z);                           \
                Bs[r][c4 * 4 + 3] = f2tf32(bReg[it].w);                           \
            }                                                                     \
        }

    float acc[2][4][4];
    #pragma unroll
    for (int i = 0; i < 2; i++)
        #pragma unroll
        for (int j = 0; j < 4; j++)
            #pragma unroll
            for (int t2 = 0; t2 < 4; t2++) acc[i][j][t2] = 0.f;

    LOAD_A_REG(0); LOAD_B_REG(0);
    STORE_TILES();
    __syncthreads();

    for (int k0 = 0; k0 < 256; k0 += GK) {
        int kn = k0 + GK;
        if (kn < 256) { LOAD_A_REG(kn); LOAD_B_REG(kn); }

        #pragma unroll
        for (int kk = 0; kk < GK; kk += 8) {
            uint32_t a[2][4];
            #pragma unroll
            for (int mf = 0; mf < 2; mf++) {
                int row0 = warpM * 32 + mf * 16;
                a[mf][0] = As[kk + qid][row0 + grp];
                a[mf][1] = As[kk + qid][row0 + 8 + grp];
                a[mf][2] = As[kk + 4 + qid][row0 + grp];
                a[mf][3] = As[kk + 4 + qid][row0 + 8 + grp];
            }
            uint32_t bf[4][2];
            #pragma unroll
            for (int nf = 0; nf < 4; nf++) {
                int col0 = warpN * 32 + nf * 8;
                bf[nf][0] = Bs[kk + qid][col0 + grp];
                bf[nf][1] = Bs[kk + 4 + qid][col0 + grp];
            }
            #pragma unroll
            for (int mf = 0; mf < 2; mf++)
                #pragma unroll
                for (int nf = 0; nf < 4; nf++) {
                    asm volatile(
                        "mma.sync.aligned.m16n8k8.row.col.f32.tf32.tf32.f32 "
                        "{%0,%1,%2,%3}, {%4,%5,%6,%7}, {%8,%9}, {%0,%1,%2,%3};\n"
                        : "+f"(acc[mf][nf][0]), "+f"(acc[mf][nf][1]),
                          "+f"(acc[mf][nf][2]), "+f"(acc[mf][nf][3])
                        : "r"(a[mf][0]), "r"(a[mf][1]), "r"(a[mf][2]), "r"(a[mf][3]),
                          "r"(bf[nf][0]), "r"(bf[nf][1]));
                }
        }
        __syncthreads();
        if (kn < 256) {
            STORE_TILES();
            __syncthreads();
        }
    }

    #pragma unroll
    for (int mf = 0; mf < 2; mf++) {
        #pragma unroll
        for (int nf = 0; nf < 4; nf++) {
            int row = rowBase + warpM * 32 + mf * 16 + grp;
            int col = colBase + warpN * 32 + nf * 8 + qid * 2;
            if (row < N) {
                g_pre[row * 512 + col]     = acc[mf][nf][0] + g_ball[col];
                g_pre[row * 512 + col + 1] = acc[mf][nf][1] + g_ball[col + 1];
            }
            if (row + 8 < N) {
                g_pre[(row + 8) * 512 + col]     = acc[mf][nf][2] + g_ball[col];
                g_pre[(row + 8) * 512 + col + 1] = acc[mf][nf][3] + g_ball[col + 1];
            }
        }
    }
}

// ---------------- stage 7: LSTM pointwise epilogue ----------------
__global__ void k_epilogue(const float* __restrict__ C, float* __restrict__ out, int N) {
    int idx = blockIdx.x * blockDim.x + threadIdx.x;
    if (idx >= N * FDIM) return;
    int n = idx >> 7, j = idx & 127;
    const float* p = g_pre + n * 512;
    float I  = 1.f / (1.f + __expf(-p[j]));
    float Fg = 1.f / (1.f + __expf(-p[128 + j]));
    float O  = 1.f / (1.f + __expf(-p[256 + j]));
    float Ct = tanhf(p[384 + j]);
    float Cn = Ct * I + Fg * C[idx];
    float Hn = O * tanhf(Cn);
    out[idx] = Hn;               // H_new
    out[N * FDIM + idx] = Cn;    // C_new
}

// ---------------- launch (fork/join: weights branch overlaps graph chain) ----------------
extern "C" void kernel_launch(void* const* d_in, const int* in_sizes, int n_in,
                              void* d_out, int out_size) {
    const float* X  = (const float*)d_in[0];
    const int*   ei = (const int*)d_in[1];      // edge_index is int32 (JAX x64 disabled)
    const float* ew = (const float*)d_in[2];
    const float* H  = (const float*)d_in[3];
    const float* C  = (const float*)d_in[4];
    const float *Wc_i = (const float*)d_in[5],  *bc_i = (const float*)d_in[6],
                *Wl_i = (const float*)d_in[7],  *bl_i = (const float*)d_in[8];
    const float *Wc_f = (const float*)d_in[9],  *bc_f = (const float*)d_in[10],
                *Wl_f = (const float*)d_in[11], *bl_f = (const float*)d_in[12];
    const float *Wc_o = (const float*)d_in[13], *bc_o = (const float*)d_in[14],
                *Wl_o = (const float*)d_in[15], *bl_o = (const float*)d_in[16];
    const float *Wl_ct = (const float*)d_in[19], *bl_ct = (const float*)d_in[20];

    int N = in_sizes[0] / FDIM;
    int E = in_sizes[2];

    float* out = (float*)d_out;

    cudaStream_t s2;
    cudaStreamCreateWithFlags(&s2, cudaStreamNonBlocking);
    cudaEvent_t evFork, evJoin;
    cudaEventCreateWithFlags(&evFork, cudaEventDisableTiming);
    cudaEventCreateWithFlags(&evJoin, cudaEventDisableTiming);

    // fork: weights branch (depends only on inputs)
    cudaEventRecord(evFork, 0);
    cudaStreamWaitEvent(s2, evFork, 0);
    k_weights<<<81, 1024, 0, s2>>>(Wc_i, Wc_f, Wc_o,
                                   Wl_i, Wl_f, Wl_o, Wl_ct,
                                   bc_i, bc_f, bc_o,
                                   bl_i, bl_f, bl_o, bl_ct);
    cudaEventRecord(evJoin, s2);

    // main chain
    k_init<<<(N + 255) / 256, 256>>>(N);
    k_edge_deg<<<(E + 255) / 256, 256>>>(ei, ew, E, N);
    k_midA<<<11, 1024>>>(N, E);
    k_scatter<<<(E + 255) / 256, 256>>>(ei, ew, E, N);
    k_aggregate<<<(N * 32 + 255) / 256, 256>>>(X, N);

    // join before GEMM (needs g_Wall/g_ball)
    cudaStreamWaitEvent(0, evJoin, 0);
    dim3 gg(512 / GN, (N + GM - 1) / GM);
    k_gemm_tc<<<gg, 256>>>(H, N);
    k_epilogue<<<(N * FDIM + 255) / 256, 256>>>(C, out, N);
}